// round 2
// baseline (speedup 1.0000x reference)
#include <cuda_runtime.h>
#include <cstdint>

// Problem constants
#define B_   32
#define C_   64
#define HW_  1024
#define N_   32768          // B*H*W
#define K_   1024
#define TM   128            // points per block tile
#define TK   128            // codes per smem tile

// Scratch (no cudaMalloc allowed)
__device__ float g_cbT[C_ * K_];   // transposed codebook [c][k]
__device__ float g_hn[K_];         // 0.5*||c_k||^2

// ---------------------------------------------------------------------------
// Prep: transpose codebook + half-norms. grid 4 x 256 (one thread per code).
// ---------------------------------------------------------------------------
__global__ void prep_kernel(const float* __restrict__ cb) {
    int k = blockIdx.x * blockDim.x + threadIdx.x;   // 0..1023
    float s = 0.f;
#pragma unroll
    for (int c = 0; c < C_; ++c) {
        float v = cb[k * C_ + c];
        s += v * v;
        g_cbT[c * K_ + k] = v;                       // coalesced store along k
    }
    g_hn[k] = 0.5f * s;
}

// ---------------------------------------------------------------------------
// Main: 128-point x 128-code tiles, fp32x2 packed FMA micro-kernel, argmin,
// shuffle reduction, smem-staged gather.
// ---------------------------------------------------------------------------
__global__ __launch_bounds__(256, 2)
void vq_kernel(const float* __restrict__ z, const float* __restrict__ cb,
               float* __restrict__ out) {
    extern __shared__ float smem[];
    float* xs   = smem;                 // [64][128]  -z tile (point-major cols)
    float* cs   = smem + 8192;          // [64][128]  codebook tile
    float* hns  = smem + 16384;         // [128] half norms
    int*   sidx = (int*)(smem + 16512); // [128] winning index per point

    const int tid = threadIdx.x;
    const int tile = blockIdx.x;        // 0..255 ; 128 consecutive points, one b
    const int n0  = tile * TM;
    const int b   = n0 / HW_;
    const int hw0 = n0 % HW_;
    const float* zb = z + (size_t)b * C_ * HW_ + hw0;

    // ---- load x tile (negated), coalesced float4 ----
    {
        int m4 = (tid & 31) * 4;
        int c0 = tid >> 5;              // 0..7
#pragma unroll
        for (int cc = 0; cc < 8; ++cc) {
            int c = c0 + cc * 8;
            float4 v = *(const float4*)&zb[c * HW_ + m4];
            v.x = -v.x; v.y = -v.y; v.z = -v.z; v.w = -v.w;
            *(float4*)&xs[c * TM + m4] = v;
        }
    }

    const int tx  = tid & 15;           // code-column group
    const int ty  = tid >> 4;           // point-row group
    const int tx4 = tx * 4, ty4 = ty * 4;

    float bv[8];
    int   bi[8];
#pragma unroll
    for (int i = 0; i < 8; ++i) { bv[i] = 3.4e38f; bi[i] = 0; }

    for (int kt = 0; kt < 8; ++kt) {
        __syncthreads();                // prev iter's cs readers done
        // ---- load code tile from transposed codebook (coalesced) ----
        {
            int k4 = (tid & 31) * 4;
            int c0 = tid >> 5;
#pragma unroll
            for (int cc = 0; cc < 8; ++cc) {
                int c = c0 + cc * 8;
                *(float4*)&cs[c * TK + k4] =
                    *(const float4*)&g_cbT[c * K_ + kt * TK + k4];
            }
            if (tid < TK) hns[tid] = g_hn[kt * TK + tid];
        }
        __syncthreads();

        // ---- accumulators start at 0.5*||c||^2 (packed f32x2 pairs) ----
        unsigned long long acc[8][4];
        {
            ulonglong2 ha = *(ulonglong2*)&hns[tx4];
            ulonglong2 hb = *(ulonglong2*)&hns[64 + tx4];
#pragma unroll
            for (int i = 0; i < 8; ++i) {
                acc[i][0] = ha.x; acc[i][1] = ha.y;
                acc[i][2] = hb.x; acc[i][3] = hb.y;
            }
        }

        // ---- FFMA2 mainloop: score += (-x) * c  -> 0.5||c||^2 - x.c ----
#pragma unroll 4
        for (int c = 0; c < C_; ++c) {
            float4 xa = *(float4*)&xs[c * TM + ty4];
            float4 xb = *(float4*)&xs[c * TM + 64 + ty4];
            ulonglong2 ca  = *(ulonglong2*)&cs[c * TK + tx4];
            ulonglong2 cbp = *(ulonglong2*)&cs[c * TK + 64 + tx4];
            unsigned long long cf0 = ca.x,  cf1 = ca.y;
            unsigned long long cf2 = cbp.x, cf3 = cbp.y;
            float xv[8] = {xa.x, xa.y, xa.z, xa.w, xb.x, xb.y, xb.z, xb.w};
#pragma unroll
            for (int i = 0; i < 8; ++i) {
                unsigned long long xd;
                asm("mov.b64 %0, {%1, %1};"
                    : "=l"(xd) : "r"(__float_as_uint(xv[i])));
                asm("fma.rn.f32x2 %0, %1, %2, %0;" : "+l"(acc[i][0]) : "l"(xd), "l"(cf0));
                asm("fma.rn.f32x2 %0, %1, %2, %0;" : "+l"(acc[i][1]) : "l"(xd), "l"(cf1));
                asm("fma.rn.f32x2 %0, %1, %2, %0;" : "+l"(acc[i][2]) : "l"(xd), "l"(cf2));
                asm("fma.rn.f32x2 %0, %1, %2, %0;" : "+l"(acc[i][3]) : "l"(xd), "l"(cf3));
            }
        }

        // ---- running argmin update (ascending column order => first-wins) ----
        const int kbase = kt * TK;
#pragma unroll
        for (int i = 0; i < 8; ++i) {
#pragma unroll
            for (int p = 0; p < 4; ++p) {
                float vlo = __uint_as_float((unsigned int)acc[i][p]);
                float vhi = __uint_as_float((unsigned int)(acc[i][p] >> 32));
                int col = (p < 2) ? (tx4 + 2 * p) : (64 + tx4 + 2 * (p - 2));
                if (vlo < bv[i]) { bv[i] = vlo; bi[i] = kbase + col; }
                if (vhi < bv[i]) { bv[i] = vhi; bi[i] = kbase + col + 1; }
            }
        }
    }

    // ---- reduce across the 16 threads sharing each point row ----
#pragma unroll
    for (int i = 0; i < 8; ++i) {
#pragma unroll
        for (int off = 8; off > 0; off >>= 1) {
            float ov = __shfl_xor_sync(0xffffffffu, bv[i], off, 16);
            int   oi = __shfl_xor_sync(0xffffffffu, bi[i], off, 16);
            if (ov < bv[i] || (ov == bv[i] && oi < bi[i])) { bv[i] = ov; bi[i] = oi; }
        }
    }
    __syncthreads();
    if (tx == 0) {
#pragma unroll
        for (int i = 0; i < 8; ++i) {
            int row = (i < 4) ? (ty4 + i) : (64 + ty4 + (i - 4));
            sidx[row] = bi[i];
        }
    }
    __syncthreads();

    // ---- indices output (as float, after the codes block) ----
    float* outIdx = out + (size_t)B_ * C_ * HW_;    // offset 2097152
    if (tid < TM) outIdx[n0 + tid] = (float)sidx[tid];

    // ---- gather winning codebook rows -> smem (pad 65, conflict-free read) ----
    float* scodes = smem;   // reuse xs/cs region: 128*65 = 8320 floats (< 16384)
    {
        int c4 = (tid & 15) * 4;
        int m0 = tid >> 4;                          // 0..15
#pragma unroll
        for (int pass = 0; pass < 8; ++pass) {
            int m = m0 + pass * 16;
            int row = sidx[m];
            float4 v = *(const float4*)&cb[row * C_ + c4];
            scodes[m * 65 + c4 + 0] = v.x;
            scodes[m * 65 + c4 + 1] = v.y;
            scodes[m * 65 + c4 + 2] = v.z;
            scodes[m * 65 + c4 + 3] = v.w;
        }
    }
    __syncthreads();

    // ---- coalesced [B,C,H,W] writes ----
    {
        int m  = tid & 127;
        int ch = tid >> 7;                          // 0 or 1
        float* ob = out + (size_t)b * C_ * HW_ + hw0;
#pragma unroll
        for (int j = 0; j < 32; ++j) {
            int c = ch * 32 + j;
            ob[c * HW_ + m] = scodes[m * 65 + c];
        }
    }
}

// ---------------------------------------------------------------------------
extern "C" void kernel_launch(void* const* d_in, const int* in_sizes, int n_in,
                              void* d_out, int out_size) {
    const float* z  = (const float*)d_in[0];
    const float* cb = (const float*)d_in[1];
    float* out = (float*)d_out;

    (void)in_sizes; (void)n_in; (void)out_size;

    cudaFuncSetAttribute(vq_kernel,
                         cudaFuncAttributeMaxDynamicSharedMemorySize, 66560);

    prep_kernel<<<4, 256>>>(cb);
    vq_kernel<<<256, 256, 66560>>>(z, cb, out);
}

// round 3
// speedup vs baseline: 1.0354x; 1.0354x over previous
#include <cuda_runtime.h>
#include <cstdint>

// Problem constants
#define B_   32
#define C_   64
#define HW_  1024
#define N_   32768          // B*H*W
#define K_   1024
#define TM   128            // points per block tile
#define TK   128            // codes per K-split

// Scratch (no cudaMalloc allowed)
__device__ float g_cbT[C_ * K_];                 // transposed codebook [c][k]
__device__ float g_hn[K_];                       // 0.5*||c_k||^2
__device__ unsigned long long g_best[N_];        // packed (monotone dist | idx)

// ---------------------------------------------------------------------------
// Init: g_best = +inf key
// ---------------------------------------------------------------------------
__global__ void init_kernel() {
    int i = blockIdx.x * blockDim.x + threadIdx.x;
    g_best[i] = 0xFFFFFFFFFFFFFFFFull;
}

// ---------------------------------------------------------------------------
// Prep: transpose codebook + half-norms. grid 4 x 256 (one thread per code).
// ---------------------------------------------------------------------------
__global__ void prep_kernel(const float* __restrict__ cb) {
    int k = blockIdx.x * blockDim.x + threadIdx.x;   // 0..1023
    float s = 0.f;
#pragma unroll
    for (int c = 0; c < C_; ++c) {
        float v = cb[k * C_ + c];
        s += v * v;
        g_cbT[c * K_ + k] = v;                       // coalesced store along k
    }
    g_hn[k] = 0.5f * s;
}

// Monotone float->uint mapping (preserves total order incl. negatives)
__device__ __forceinline__ unsigned int fkey(float f) {
    unsigned int u = __float_as_uint(f);
    return (u & 0x80000000u) ? ~u : (u | 0x80000000u);
}

// ---------------------------------------------------------------------------
// Main: one block = 128 points x 128 codes (one K-split). 2048 blocks total.
// FFMA2 packed micro-kernel, per-block argmin, atomicMin combine.
// ---------------------------------------------------------------------------
__global__ __launch_bounds__(256, 2)
void vq_kernel(const float* __restrict__ z) {
    extern __shared__ float smem[];
    float* xs  = smem;                 // [64][128]  -z tile (point-major cols)
    float* cs  = smem + 8192;          // [64][128]  codebook K-split tile
    float* hns = smem + 16384;         // [128] half norms

    const int tid  = threadIdx.x;
    const int tile = blockIdx.x >> 3;          // 0..255 point tile
    const int ks   = blockIdx.x & 7;           // 0..7   K-split
    const int n0   = tile * TM;
    const int b    = n0 / HW_;
    const int hw0  = n0 % HW_;
    const float* zb = z + (size_t)b * C_ * HW_ + hw0;

    // ---- load x tile (negated) + code tile + half norms, coalesced ----
    {
        int m4 = (tid & 31) * 4;
        int c0 = tid >> 5;              // 0..7
#pragma unroll
        for (int cc = 0; cc < 8; ++cc) {
            int c = c0 + cc * 8;
            float4 v = *(const float4*)&zb[c * HW_ + m4];
            v.x = -v.x; v.y = -v.y; v.z = -v.z; v.w = -v.w;
            *(float4*)&xs[c * TM + m4] = v;
            *(float4*)&cs[c * TK + m4] =
                *(const float4*)&g_cbT[c * K_ + ks * TK + m4];
        }
        if (tid < TK) hns[tid] = g_hn[ks * TK + tid];
    }
    __syncthreads();

    const int tx  = tid & 15;           // code-column group
    const int ty  = tid >> 4;           // point-row group
    const int tx4 = tx * 4, ty4 = ty * 4;

    // ---- accumulators start at 0.5*||c||^2 (packed f32x2 pairs) ----
    unsigned long long acc[8][4];
    {
        ulonglong2 ha = *(ulonglong2*)&hns[tx4];
        ulonglong2 hb = *(ulonglong2*)&hns[64 + tx4];
#pragma unroll
        for (int i = 0; i < 8; ++i) {
            acc[i][0] = ha.x; acc[i][1] = ha.y;
            acc[i][2] = hb.x; acc[i][3] = hb.y;
        }
    }

    // ---- FFMA2 mainloop: score += (-x) * c  -> 0.5||c||^2 - x.c ----
#pragma unroll 4
    for (int c = 0; c < C_; ++c) {
        float4 xa = *(float4*)&xs[c * TM + ty4];
        float4 xb = *(float4*)&xs[c * TM + 64 + ty4];
        ulonglong2 ca  = *(ulonglong2*)&cs[c * TK + tx4];
        ulonglong2 cbp = *(ulonglong2*)&cs[c * TK + 64 + tx4];
        unsigned long long cf0 = ca.x,  cf1 = ca.y;
        unsigned long long cf2 = cbp.x, cf3 = cbp.y;
        float xv[8] = {xa.x, xa.y, xa.z, xa.w, xb.x, xb.y, xb.z, xb.w};
#pragma unroll
        for (int i = 0; i < 8; ++i) {
            unsigned long long xd;
            asm("mov.b64 %0, {%1, %1};"
                : "=l"(xd) : "r"(__float_as_uint(xv[i])));
            asm("fma.rn.f32x2 %0, %1, %2, %0;" : "+l"(acc[i][0]) : "l"(xd), "l"(cf0));
            asm("fma.rn.f32x2 %0, %1, %2, %0;" : "+l"(acc[i][1]) : "l"(xd), "l"(cf1));
            asm("fma.rn.f32x2 %0, %1, %2, %0;" : "+l"(acc[i][2]) : "l"(xd), "l"(cf2));
            asm("fma.rn.f32x2 %0, %1, %2, %0;" : "+l"(acc[i][3]) : "l"(xd), "l"(cf3));
        }
    }

    // ---- per-thread argmin (ascending column order => first-wins on ties) ----
    const int kbase = ks * TK;
    float bv[8];
    int   bi[8];
#pragma unroll
    for (int i = 0; i < 8; ++i) { bv[i] = 3.4e38f; bi[i] = 0x7fffffff; }
#pragma unroll
    for (int i = 0; i < 8; ++i) {
#pragma unroll
        for (int p = 0; p < 4; ++p) {
            float vlo = __uint_as_float((unsigned int)acc[i][p]);
            float vhi = __uint_as_float((unsigned int)(acc[i][p] >> 32));
            int col = (p < 2) ? (tx4 + 2 * p) : (64 + tx4 + 2 * (p - 2));
            if (vlo < bv[i]) { bv[i] = vlo; bi[i] = kbase + col; }
            if (vhi < bv[i]) { bv[i] = vhi; bi[i] = kbase + col + 1; }
        }
    }

    // ---- reduce across the 16 threads sharing each point row ----
#pragma unroll
    for (int i = 0; i < 8; ++i) {
#pragma unroll
        for (int off = 8; off > 0; off >>= 1) {
            float ov = __shfl_xor_sync(0xffffffffu, bv[i], off, 16);
            int   oi = __shfl_xor_sync(0xffffffffu, bi[i], off, 16);
            if (ov < bv[i] || (ov == bv[i] && oi < bi[i])) { bv[i] = ov; bi[i] = oi; }
        }
    }

    // ---- combine across K-splits with monotone-packed atomicMin ----
    if (tx == 0) {
#pragma unroll
        for (int i = 0; i < 8; ++i) {
            int row = (i < 4) ? (ty4 + i) : (64 + ty4 + (i - 4));
            unsigned long long key =
                ((unsigned long long)fkey(bv[i]) << 32) | (unsigned int)bi[i];
            atomicMin(&g_best[n0 + row], key);
        }
    }
}

// ---------------------------------------------------------------------------
// Finalize: read winners, write indices (as float) + gathered codes.
// 256 blocks x 256 threads; one block = 128 points.
// ---------------------------------------------------------------------------
__global__ __launch_bounds__(256)
void finalize_kernel(const float* __restrict__ cb, float* __restrict__ out) {
    __shared__ float scodes[TM * 65];
    __shared__ int   sidx[TM];

    const int tid  = threadIdx.x;
    const int tile = blockIdx.x;
    const int n0   = tile * TM;
    const int b    = n0 / HW_;
    const int hw0  = n0 % HW_;

    if (tid < TM) {
        unsigned long long key = g_best[n0 + tid];
        int idx = (int)(unsigned int)(key & 0xFFFFFFFFull);
        sidx[tid] = idx;
        // indices output (as float) after the codes block
        out[(size_t)B_ * C_ * HW_ + n0 + tid] = (float)idx;
    }
    __syncthreads();

    // gather winning codebook rows -> smem (pad 65, conflict-free read)
    {
        int c4 = (tid & 15) * 4;
        int m0 = tid >> 4;                          // 0..15
#pragma unroll
        for (int pass = 0; pass < 8; ++pass) {
            int m = m0 + pass * 16;
            int row = sidx[m];
            float4 v = *(const float4*)&cb[row * C_ + c4];
            scodes[m * 65 + c4 + 0] = v.x;
            scodes[m * 65 + c4 + 1] = v.y;
            scodes[m * 65 + c4 + 2] = v.z;
            scodes[m * 65 + c4 + 3] = v.w;
        }
    }
    __syncthreads();

    // coalesced [B,C,H,W] writes
    {
        int m  = tid & 127;
        int ch = tid >> 7;                          // 0 or 1
        float* ob = out + (size_t)b * C_ * HW_ + hw0;
#pragma unroll
        for (int j = 0; j < 32; ++j) {
            int c = ch * 32 + j;
            ob[c * HW_ + m] = scodes[m * 65 + c];
        }
    }
}

// ---------------------------------------------------------------------------
extern "C" void kernel_launch(void* const* d_in, const int* in_sizes, int n_in,
                              void* d_out, int out_size) {
    const float* z  = (const float*)d_in[0];
    const float* cb = (const float*)d_in[1];
    float* out = (float*)d_out;

    (void)in_sizes; (void)n_in; (void)out_size;

    cudaFuncSetAttribute(vq_kernel,
                         cudaFuncAttributeMaxDynamicSharedMemorySize, 66048);

    init_kernel<<<64, 512>>>();
    prep_kernel<<<4, 256>>>(cb);
    vq_kernel<<<2048, 256, 66048>>>(z);
    finalize_kernel<<<256, 256>>>(cb, out);
}